// round 12
// baseline (speedup 1.0000x reference)
#include <cuda_runtime.h>
#include <cuda_bf16.h>
#include <cuda_fp16.h>
#include <cstdint>

// ---------------------------------------------------------------------------
// Fused transformer block, fp32 in/out.
//   qkv = x @ Wqkv^T + bqkv   (4096x3072x1024)  fp16 HMMA (fp16 acc + fp32
//   attention: 16 heads, d=64, scale 1/32        promotion per 64-K chunk)
//   out = attn @ W1^T + b1    (4096x1024x1024)
// R12: GEMMs use f16-accumulate m16n8k16 (potential 2x HMMA rate), promoting
// partial sums to fp32 once per K-tile (64) to bound accumulation error.
// ---------------------------------------------------------------------------

#define BATCH   4
#define SEQ     1024
#define DIM     1024
#define HEADS   16
#define HDIM    64
#define ROWS    (BATCH * SEQ)      // 4096
#define QKVDIM  (3 * DIM)          // 3072

__device__ __align__(256) __half g_qkv_h[ROWS * QKVDIM];
__device__ __align__(256) __half g_attn_h[ROWS * DIM];
__device__ __align__(256) __half g_xh[ROWS * DIM];
__device__ __align__(256) __half g_wh[QKVDIM * DIM];
__device__ __align__(256) __half g_w1h[DIM * DIM];

// ===========================================================================
// helpers
// ===========================================================================
__device__ __forceinline__ uint32_t smem_u32(const void* p) {
    uint32_t a;
    asm("{ .reg .u64 t; cvta.to.shared.u64 t, %1; cvt.u32.u64 %0, t; }"
        : "=r"(a) : "l"(p));
    return a;
}
__device__ __forceinline__ void cp16(uint32_t dst, const void* src) {
    asm volatile("cp.async.cg.shared.global [%0], [%1], 16;" :: "r"(dst), "l"(src));
}
#define CP_COMMIT() asm volatile("cp.async.commit_group;" ::: "memory")
#define CP_WAIT(n)  asm volatile("cp.async.wait_group %0;" :: "n"(n) : "memory")

// fp16 m16n8k16, fp32 accumulate (attention)
__device__ __forceinline__ void mma_16n8k16_f16(
    float* c, const uint32_t* a, const uint32_t* b)
{
    asm volatile(
        "mma.sync.aligned.m16n8k16.row.col.f32.f16.f16.f32 "
        "{%0,%1,%2,%3}, {%4,%5,%6,%7}, {%8,%9}, {%0,%1,%2,%3};"
        : "+f"(c[0]), "+f"(c[1]), "+f"(c[2]), "+f"(c[3])
        : "r"(a[0]), "r"(a[1]), "r"(a[2]), "r"(a[3]), "r"(b[0]), "r"(b[1]));
}

// fp16 m16n8k16, fp16 accumulate (GEMMs; promoted to fp32 per K-chunk)
__device__ __forceinline__ void mma_16n8k16_h16(
    uint32_t* d, const uint32_t* a, const uint32_t* b)
{
    asm volatile(
        "mma.sync.aligned.m16n8k16.row.col.f16.f16.f16.f16 "
        "{%0,%1}, {%2,%3,%4,%5}, {%6,%7}, {%0,%1};"
        : "+r"(d[0]), "+r"(d[1])
        : "r"(a[0]), "r"(a[1]), "r"(a[2]), "r"(a[3]), "r"(b[0]), "r"(b[1]));
}

__device__ __forceinline__ void ldmx4(
    uint32_t& r0, uint32_t& r1, uint32_t& r2, uint32_t& r3, uint32_t addr)
{
    asm volatile(
        "ldmatrix.sync.aligned.m8n8.x4.shared.b16 {%0,%1,%2,%3}, [%4];"
        : "=r"(r0), "=r"(r1), "=r"(r2), "=r"(r3) : "r"(addr));
}
__device__ __forceinline__ void ldmx4t(
    uint32_t& r0, uint32_t& r1, uint32_t& r2, uint32_t& r3, uint32_t addr)
{
    asm volatile(
        "ldmatrix.sync.aligned.m8n8.x4.trans.shared.b16 {%0,%1,%2,%3}, [%4];"
        : "=r"(r0), "=r"(r1), "=r"(r2), "=r"(r3) : "r"(addr));
}

// ===========================================================================
// fp32 -> fp16 conversion kernel
// ===========================================================================
__global__ __launch_bounds__(256) void to_half(
    const float* __restrict__ in, __half* __restrict__ out, int n2)
{
    int i = blockIdx.x * blockDim.x + threadIdx.x;
    if (i >= n2) return;
    float2 v = ((const float2*)in)[i];
    ((__half2*)out)[i] = __floats2half2_rn(v.x, v.y);
}

// ===========================================================================
// fp16 NT GEMM + bias:  C[M,N] = A[M,K] @ B[N,K]^T + bias[N]
// CTA tile 128x256, K-tile 64, 2-stage cp.async, 256 thr,
// warp grid 2x4, warp tile 64x64, m16n8k16 with FP16 accumulate;
// partial sums promoted to fp32 once per K-tile (chunk error ~1e-4).
// ===========================================================================
#define HTK       64
#define HROWB     144
#define HATILE    (128 * HROWB)
#define HBTILE    (256 * HROWB)
#define HSTAGE    (HATILE + HBTILE)          // 55296
#define HGEMM_SMEM (2 * HSTAGE)              // 110592 B

template <bool HALF_OUT>
__global__ __launch_bounds__(256) void gemm_mma_f16(
    const __half* __restrict__ A, const __half* __restrict__ B,
    const float* __restrict__ bias, void* __restrict__ Cout,
    int M, int N, int K)
{
    extern __shared__ char smem[];
    const uint32_t sb = smem_u32(smem);
    const int tid    = threadIdx.x;
    const int wid    = tid >> 5;
    const int lane   = tid & 31;
    const int g      = lane >> 2;
    const int tig    = lane & 3;
    const int warp_m = wid & 1;
    const int warp_n = wid >> 1;
    const int m0     = blockIdx.y * 128;
    const int n0     = blockIdx.x * 256;

    const int lr  = lane & 7;
    const int grp = lane >> 3;
    const int s1  = grp & 1;
    const int s2  = grp >> 1;
    const int knt = grp >> 1;
    const int kkh = grp & 1;

    float c[4][8][4];
#pragma unroll
    for (int mt = 0; mt < 4; mt++)
#pragma unroll
        for (int nt = 0; nt < 8; nt++)
#pragma unroll
            for (int r = 0; r < 4; r++) c[mt][nt][r] = 0.0f;

    uint32_t ch[4][8][2];
#pragma unroll
    for (int mt = 0; mt < 4; mt++)
#pragma unroll
        for (int nt = 0; nt < 8; nt++) { ch[mt][nt][0] = 0u; ch[mt][nt][1] = 0u; }

    auto load_tile = [&](int slot, int k0) {
        const uint32_t aB = sb + slot * HSTAGE;
        const uint32_t bB = aB + HATILE;
#pragma unroll
        for (int i = 0; i < 4; i++) {
            const int idx = i * 256 + tid;
            const int row = idx >> 3;
            const int seg = idx & 7;
            cp16(aB + row * HROWB + seg * 16, A + (size_t)(m0 + row) * K + k0 + seg * 8);
        }
#pragma unroll
        for (int i = 0; i < 8; i++) {
            const int idx = i * 256 + tid;
            const int row = idx >> 3;
            const int seg = idx & 7;
            cp16(bB + row * HROWB + seg * 16, B + (size_t)(n0 + row) * K + k0 + seg * 8);
        }
        CP_COMMIT();
    };

    const int NT = K / HTK;
    load_tile(0, 0);

    for (int t = 0; t < NT; t++) {
        if (t + 1 < NT) {
            load_tile((t + 1) & 1, (t + 1) * HTK);
            CP_WAIT(1);
        } else {
            CP_WAIT(0);
        }
        __syncthreads();

        const uint32_t aB = sb + (t & 1) * HSTAGE;
        const uint32_t bB = aB + HATILE;

#pragma unroll
        for (int ks = 0; ks < 4; ks++) {
            uint32_t af[4][4];
            uint32_t bf[8][2];
            const uint32_t arow = aB + (warp_m * 64 + lr + 8 * s1) * HROWB
                                     + (ks * 16 + 8 * s2) * 2;
#pragma unroll
            for (int mt = 0; mt < 4; mt++)
                ldmx4(af[mt][0], af[mt][1], af[mt][2], af[mt][3],
                      arow + mt * 16 * HROWB);
            const uint32_t brow = bB + (warp_n * 64 + knt * 8 + lr) * HROWB
                                     + (ks * 16 + kkh * 8) * 2;
#pragma unroll
            for (int i = 0; i < 4; i++)
                ldmx4(bf[2 * i][0], bf[2 * i][1], bf[2 * i + 1][0], bf[2 * i + 1][1],
                      brow + i * 16 * HROWB);
#pragma unroll
            for (int mt = 0; mt < 4; mt++)
#pragma unroll
                for (int nt = 0; nt < 8; nt++)
                    mma_16n8k16_h16(ch[mt][nt], af[mt], bf[nt]);
        }

        // promote fp16 partials -> fp32 accumulators (one K-tile chunk)
#pragma unroll
        for (int mt = 0; mt < 4; mt++)
#pragma unroll
            for (int nt = 0; nt < 8; nt++) {
                const float2 f0 = __half22float2(*(__half2*)&ch[mt][nt][0]);
                const float2 f1 = __half22float2(*(__half2*)&ch[mt][nt][1]);
                c[mt][nt][0] += f0.x; c[mt][nt][1] += f0.y;
                c[mt][nt][2] += f1.x; c[mt][nt][3] += f1.y;
                ch[mt][nt][0] = 0u;   ch[mt][nt][1] = 0u;
            }
        __syncthreads();
    }

#pragma unroll
    for (int mt = 0; mt < 4; mt++) {
        const int row = m0 + warp_m * 64 + mt * 16 + g;
#pragma unroll
        for (int nt = 0; nt < 8; nt++) {
            const int col = n0 + warp_n * 64 + nt * 8 + tig * 2;
            const float bx = bias[col];
            const float by = bias[col + 1];
            if (HALF_OUT) {
                __half* C = (__half*)Cout;
                *(__half2*)(C + (size_t)row * N + col) =
                    __floats2half2_rn(c[mt][nt][0] + bx, c[mt][nt][1] + by);
                *(__half2*)(C + (size_t)(row + 8) * N + col) =
                    __floats2half2_rn(c[mt][nt][2] + bx, c[mt][nt][3] + by);
            } else {
                float* C = (float*)Cout;
                *(float2*)(C + (size_t)row * N + col) =
                    make_float2(c[mt][nt][0] + bx, c[mt][nt][1] + by);
                *(float2*)(C + (size_t)(row + 8) * N + col) =
                    make_float2(c[mt][nt][2] + bx, c[mt][nt][3] + by);
            }
        }
    }
}

// ===========================================================================
// fp16 flash attention (unchanged from R10/R11, passing).
// ===========================================================================
#define FAS       144
#define FA_Q      0
#define FA_TILE   (64 * FAS)
#define FA_K      FA_TILE
#define FA_V      (FA_K + 2 * FA_TILE)
#define FA_SMEM   (FA_V + 2 * FA_TILE)      // 46080 B

__global__ __launch_bounds__(128) void flash_attn_f16(
    const __half* __restrict__ qkv, __half* __restrict__ out)
{
    extern __shared__ char smem[];
    const uint32_t sb = smem_u32(smem);
    const int tid  = threadIdx.x;
    const int wid  = tid >> 5;
    const int lane = tid & 31;
    const int g    = lane >> 2;
    const int tig  = lane & 3;
    const int q0   = blockIdx.x * 64;
    const int h    = blockIdx.y;
    const int b    = blockIdx.z;

    const __half* qb = qkv + (size_t)b * SEQ * QKVDIM + (size_t)h * HDIM;
    const __half* kb = qb + DIM;
    const __half* vb = qb + 2 * DIM;

#pragma unroll
    for (int i = 0; i < 4; i++) {
        const int idx = i * 128 + tid;
        const int row = idx >> 3;
        const int seg = idx & 7;
        cp16(sb + FA_Q + row * FAS + seg * 16,
             qb + (size_t)(q0 + row) * QKVDIM + seg * 8);
    }
    CP_COMMIT();

    auto load_kv = [&](int slot, int jt) {
        const int j0 = jt * 64;
        const uint32_t kB = sb + FA_K + slot * FA_TILE;
        const uint32_t vB = sb + FA_V + slot * FA_TILE;
#pragma unroll
        for (int i = 0; i < 4; i++) {
            const int idx = i * 128 + tid;
            const int row = idx >> 3;
            const int seg = idx & 7;
            cp16(kB + row * FAS + seg * 16, kb + (size_t)(j0 + row) * QKVDIM + seg * 8);
            cp16(vB + row * FAS + seg * 16, vb + (size_t)(j0 + row) * QKVDIM + seg * 8);
        }
        CP_COMMIT();
    };

    load_kv(0, 0);
    CP_WAIT(1);
    __syncthreads();

    const int lr  = lane & 7;
    const int grp = lane >> 3;

    uint32_t qf[4][4];
    {
        const uint32_t qbase = sb + FA_Q + (wid * 16) * FAS;
        const int s1 = grp & 1;
        const int s2 = grp >> 1;
        const __half2 sc = __float2half2_rn(0.03125f);
#pragma unroll
        for (int ks = 0; ks < 4; ks++) {
            const uint32_t addr = qbase + (lr + 8 * s1) * FAS + (ks * 16 + 8 * s2) * 2;
            ldmx4(qf[ks][0], qf[ks][1], qf[ks][2], qf[ks][3], addr);
#pragma unroll
            for (int j = 0; j < 4; j++) {
                __half2 v = *(__half2*)&qf[ks][j];
                v = __hmul2(v, sc);
                qf[ks][j] = *(uint32_t*)&v;
            }
        }
    }

    float o[8][4];
#pragma unroll
    for (int nt = 0; nt < 8; nt++)
#pragma unroll
        for (int r = 0; r < 4; r++) o[nt][r] = 0.0f;
    float m_r[2] = {-1e30f, -1e30f};
    float l_r[2] = {0.0f, 0.0f};

    const int knt = grp >> 1;
    const int kkh = grp & 1;

    for (int jt = 0; jt < SEQ / 64; jt++) {
        if (jt + 1 < SEQ / 64) {
            load_kv((jt + 1) & 1, jt + 1);
            CP_WAIT(1);
        } else {
            CP_WAIT(0);
        }
        __syncthreads();

        const uint32_t kB = sb + FA_K + (jt & 1) * FA_TILE;
        const uint32_t vB = sb + FA_V + (jt & 1) * FA_TILE;

        float c[8][4];
#pragma unroll
        for (int nt = 0; nt < 8; nt++)
#pragma unroll
            for (int r = 0; r < 4; r++) c[nt][r] = 0.0f;

#pragma unroll
        for (int ks = 0; ks < 4; ks++) {
            uint32_t kf[8][2];
#pragma unroll
            for (int i = 0; i < 4; i++) {
                const uint32_t addr =
                    kB + ((2 * i + knt) * 8 + lr) * FAS + (ks * 16 + kkh * 8) * 2;
                ldmx4(kf[2 * i][0], kf[2 * i][1], kf[2 * i + 1][0], kf[2 * i + 1][1], addr);
            }
#pragma unroll
            for (int nt = 0; nt < 8; nt++)
                mma_16n8k16_f16(c[nt], qf[ks], kf[nt]);
        }

#pragma unroll
        for (int r = 0; r < 2; r++) {
            float mx = -1e30f;
#pragma unroll
            for (int nt = 0; nt < 8; nt++) {
                mx = fmaxf(mx, c[nt][2 * r]);
                mx = fmaxf(mx, c[nt][2 * r + 1]);
            }
            mx = fmaxf(mx, __shfl_xor_sync(0xffffffffu, mx, 1));
            mx = fmaxf(mx, __shfl_xor_sync(0xffffffffu, mx, 2));
            const float mnew  = fmaxf(m_r[r], mx);
            const float alpha = __expf(m_r[r] - mnew);
            float sum = 0.0f;
#pragma unroll
            for (int nt = 0; nt < 8; nt++) {
                const float p0 = __expf(c[nt][2 * r]     - mnew);
                const float p1 = __expf(c[nt][2 * r + 1] - mnew);
                c[nt][2 * r] = p0; c[nt][2 * r + 1] = p1;
                sum += p0 + p1;
            }
            sum += __shfl_xor_sync(0xffffffffu, sum, 1);
            sum += __shfl_xor_sync(0xffffffffu, sum, 2);
            l_r[r] = l_r[r] * alpha + sum;
            m_r[r] = mnew;
#pragma unroll
            for (int nt = 0; nt < 8; nt++) {
                o[nt][2 * r]     *= alpha;
                o[nt][2 * r + 1] *= alpha;
            }
        }

#pragma unroll
        for (int ks = 0; ks < 4; ks++) {
            uint32_t pa[4];
            {
                __half2 p0 = __floats2half2_rn(c[2 * ks][0],     c[2 * ks][1]);
                __half2 p1 = __floats2half2_rn(c[2 * ks][2],     c[2 * ks][3]);
                __half2 p2 = __floats2half2_rn(c[2 * ks + 1][0], c[2 * ks + 1][1]);
                __half2 p3 = __floats2half2_rn(c[2 * ks + 1][2], c[2 * ks + 1][3]);
                pa[0] = *(uint32_t*)&p0;
                pa[1] = *(uint32_t*)&p1;
                pa[2] = *(uint32_t*)&p2;
                pa[3] = *(uint32_t*)&p3;
            }
            uint32_t vf[8][2];
#pragma unroll
            for (int i = 0; i < 4; i++) {
                const uint32_t addr =
                    vB + (ks * 16 + kkh * 8 + lr) * FAS + ((2 * i + knt) * 8) * 2;
                ldmx4t(vf[2 * i][0], vf[2 * i][1], vf[2 * i + 1][0], vf[2 * i + 1][1], addr);
            }
#pragma unroll
            for (int nt = 0; nt < 8; nt++)
                mma_16n8k16_f16(o[nt], pa, vf[nt]);
        }
        __syncthreads();
    }

    const float inv0 = 1.0f / l_r[0];
    const float inv1 = 1.0f / l_r[1];
    const size_t row0 = (size_t)b * SEQ + q0 + wid * 16 + g;
    const size_t row1 = row0 + 8;
#pragma unroll
    for (int nt = 0; nt < 8; nt++) {
        const int col = h * HDIM + nt * 8 + 2 * tig;
        *(__half2*)(out + row0 * DIM + col) =
            __floats2half2_rn(o[nt][0] * inv0, o[nt][1] * inv0);
        *(__half2*)(out + row1 * DIM + col) =
            __floats2half2_rn(o[nt][2] * inv1, o[nt][3] * inv1);
    }
}

// ===========================================================================
// Launch
// ===========================================================================
extern "C" void kernel_launch(void* const* d_in, const int* in_sizes, int n_in,
                              void* d_out, int out_size)
{
    const float* x    = (const float*)d_in[0];
    const float* Wqkv = (const float*)d_in[1];
    const float* bqkv = (const float*)d_in[2];
    const float* W1   = (const float*)d_in[3];
    const float* b1   = (const float*)d_in[4];
    float* out = (float*)d_out;

    __half *qkv_p, *attn_p, *xh_p, *wh_p, *w1h_p;
    cudaGetSymbolAddress((void**)&qkv_p,  g_qkv_h);
    cudaGetSymbolAddress((void**)&attn_p, g_attn_h);
    cudaGetSymbolAddress((void**)&xh_p,   g_xh);
    cudaGetSymbolAddress((void**)&wh_p,   g_wh);
    cudaGetSymbolAddress((void**)&w1h_p,  g_w1h);

    cudaFuncSetAttribute(gemm_mma_f16<true>,
                         cudaFuncAttributeMaxDynamicSharedMemorySize, HGEMM_SMEM);
    cudaFuncSetAttribute(gemm_mma_f16<false>,
                         cudaFuncAttributeMaxDynamicSharedMemorySize, HGEMM_SMEM);
    cudaFuncSetAttribute(flash_attn_f16,
                         cudaFuncAttributeMaxDynamicSharedMemorySize, FA_SMEM);

    // 0) convert GEMM operands to fp16
    to_half<<<(ROWS * DIM / 2 + 255) / 256, 256>>>(x, xh_p, ROWS * DIM / 2);
    to_half<<<(QKVDIM * DIM / 2 + 255) / 256, 256>>>(Wqkv, wh_p, QKVDIM * DIM / 2);
    to_half<<<(DIM * DIM / 2 + 255) / 256, 256>>>(W1, w1h_p, DIM * DIM / 2);

    // 1) QKV projection -> fp16 qkv
    {
        dim3 grid(QKVDIM / 256, ROWS / 128);
        gemm_mma_f16<true><<<grid, 256, HGEMM_SMEM>>>(xh_p, wh_p, bqkv, qkv_p,
                                                      ROWS, QKVDIM, DIM);
    }

    // 2) fp16 flash attention -> fp16 attn
    {
        dim3 grid(SEQ / 64, HEADS, BATCH);
        flash_attn_f16<<<grid, 128, FA_SMEM>>>(qkv_p, attn_p);
    }

    // 3) Output projection -> fp32 out
    {
        dim3 grid(DIM / 256, ROWS / 128);
        gemm_mma_f16<false><<<grid, 256, HGEMM_SMEM>>>(attn_p, w1h_p, b1, out,
                                                       ROWS, DIM, DIM);
    }
}

// round 13
// speedup vs baseline: 1.1634x; 1.1634x over previous
#include <cuda_runtime.h>
#include <cuda_bf16.h>
#include <cuda_fp16.h>
#include <cstdint>

// ---------------------------------------------------------------------------
// Fused transformer block, fp32 in/out. All math on fp16 HMMA m16n8k16
// (fp32 accumulate — measured same HMMA rate as fp16-acc on sm_103a, without
// the promotion overhead).
//   qkv = x @ Wqkv^T + bqkv   (4096x3072x1024)  -> fp16 qkv
//   attention: 16 heads, d=64, scale 1/32       -> fp16 flash attention
//   out = attn @ W1^T + b1    (4096x1024x1024)  -> fp32 out
// R13: R11 GEMM (best measured) + single fused fp32->fp16 convert kernel.
// ---------------------------------------------------------------------------

#define BATCH   4
#define SEQ     1024
#define DIM     1024
#define HEADS   16
#define HDIM    64
#define ROWS    (BATCH * SEQ)      // 4096
#define QKVDIM  (3 * DIM)          // 3072

#define N_X   (ROWS * DIM)         // 4194304
#define N_W   (QKVDIM * DIM)       // 3145728
#define N_W1  (DIM * DIM)          // 1048576

__device__ __align__(256) __half g_qkv_h[ROWS * QKVDIM];
__device__ __align__(256) __half g_attn_h[ROWS * DIM];
__device__ __align__(256) __half g_xh[N_X];
__device__ __align__(256) __half g_wh[N_W];
__device__ __align__(256) __half g_w1h[N_W1];

// ===========================================================================
// helpers
// ===========================================================================
__device__ __forceinline__ uint32_t smem_u32(const void* p) {
    uint32_t a;
    asm("{ .reg .u64 t; cvta.to.shared.u64 t, %1; cvt.u32.u64 %0, t; }"
        : "=r"(a) : "l"(p));
    return a;
}
__device__ __forceinline__ void cp16(uint32_t dst, const void* src) {
    asm volatile("cp.async.cg.shared.global [%0], [%1], 16;" :: "r"(dst), "l"(src));
}
#define CP_COMMIT() asm volatile("cp.async.commit_group;" ::: "memory")
#define CP_WAIT(n)  asm volatile("cp.async.wait_group %0;" :: "n"(n) : "memory")

// fp16 m16n8k16, fp32 accumulate
__device__ __forceinline__ void mma_16n8k16_f16(
    float* c, const uint32_t* a, const uint32_t* b)
{
    asm volatile(
        "mma.sync.aligned.m16n8k16.row.col.f32.f16.f16.f32 "
        "{%0,%1,%2,%3}, {%4,%5,%6,%7}, {%8,%9}, {%0,%1,%2,%3};"
        : "+f"(c[0]), "+f"(c[1]), "+f"(c[2]), "+f"(c[3])
        : "r"(a[0]), "r"(a[1]), "r"(a[2]), "r"(a[3]), "r"(b[0]), "r"(b[1]));
}

__device__ __forceinline__ void ldmx4(
    uint32_t& r0, uint32_t& r1, uint32_t& r2, uint32_t& r3, uint32_t addr)
{
    asm volatile(
        "ldmatrix.sync.aligned.m8n8.x4.shared.b16 {%0,%1,%2,%3}, [%4];"
        : "=r"(r0), "=r"(r1), "=r"(r2), "=r"(r3) : "r"(addr));
}
__device__ __forceinline__ void ldmx4t(
    uint32_t& r0, uint32_t& r1, uint32_t& r2, uint32_t& r3, uint32_t addr)
{
    asm volatile(
        "ldmatrix.sync.aligned.m8n8.x4.trans.shared.b16 {%0,%1,%2,%3}, [%4];"
        : "=r"(r0), "=r"(r1), "=r"(r2), "=r"(r3) : "r"(addr));
}

// ===========================================================================
// fused fp32 -> fp16 conversion: one launch converts x, Wqkv, W1.
// 4 floats per thread (float4 load, 2x half2 store).
// ===========================================================================
#define NCONV4 ((N_X + N_W + N_W1) / 4)     // 2097152 quads

__global__ __launch_bounds__(256) void to_half_all(
    const float* __restrict__ x, const float* __restrict__ w,
    const float* __restrict__ w1,
    __half* __restrict__ xh, __half* __restrict__ wh, __half* __restrict__ w1h)
{
    int i = blockIdx.x * blockDim.x + threadIdx.x;
    if (i >= NCONV4) return;
    const float* src;
    __half* dst;
    int j = i;
    if (j < N_X / 4)            { src = x;  dst = xh;  }
    else if ((j -= N_X / 4) < N_W / 4) { src = w;  dst = wh;  }
    else { j -= N_W / 4;          src = w1; dst = w1h; }
    float4 v = ((const float4*)src)[j];
    __half2* d = (__half2*)(dst + j * 4);
    d[0] = __floats2half2_rn(v.x, v.y);
    d[1] = __floats2half2_rn(v.z, v.w);
}

// ===========================================================================
// fp16 NT GEMM + bias (R11 version, best measured):
// CTA tile 128x256, K-tile 64, 2-stage cp.async, 256 thr,
// warp grid 2x4, warp tile 64x64, m16n8k16, ldmatrix.x4 fragments.
// ===========================================================================
#define HTK       64
#define HROWB     144
#define HATILE    (128 * HROWB)
#define HBTILE    (256 * HROWB)
#define HSTAGE    (HATILE + HBTILE)          // 55296
#define HGEMM_SMEM (2 * HSTAGE)              // 110592 B

template <bool HALF_OUT>
__global__ __launch_bounds__(256) void gemm_mma_f16(
    const __half* __restrict__ A, const __half* __restrict__ B,
    const float* __restrict__ bias, void* __restrict__ Cout,
    int M, int N, int K)
{
    extern __shared__ char smem[];
    const uint32_t sb = smem_u32(smem);
    const int tid    = threadIdx.x;
    const int wid    = tid >> 5;
    const int lane   = tid & 31;
    const int g      = lane >> 2;
    const int tig    = lane & 3;
    const int warp_m = wid & 1;
    const int warp_n = wid >> 1;
    const int m0     = blockIdx.y * 128;
    const int n0     = blockIdx.x * 256;

    const int lr  = lane & 7;
    const int grp = lane >> 3;
    const int s1  = grp & 1;
    const int s2  = grp >> 1;
    const int knt = grp >> 1;
    const int kkh = grp & 1;

    float c[4][8][4];
#pragma unroll
    for (int mt = 0; mt < 4; mt++)
#pragma unroll
        for (int nt = 0; nt < 8; nt++)
#pragma unroll
            for (int r = 0; r < 4; r++) c[mt][nt][r] = 0.0f;

    auto load_tile = [&](int slot, int k0) {
        const uint32_t aB = sb + slot * HSTAGE;
        const uint32_t bB = aB + HATILE;
#pragma unroll
        for (int i = 0; i < 4; i++) {
            const int idx = i * 256 + tid;
            const int row = idx >> 3;
            const int seg = idx & 7;
            cp16(aB + row * HROWB + seg * 16, A + (size_t)(m0 + row) * K + k0 + seg * 8);
        }
#pragma unroll
        for (int i = 0; i < 8; i++) {
            const int idx = i * 256 + tid;
            const int row = idx >> 3;
            const int seg = idx & 7;
            cp16(bB + row * HROWB + seg * 16, B + (size_t)(n0 + row) * K + k0 + seg * 8);
        }
        CP_COMMIT();
    };

    auto load_frags = [&](uint32_t aB, uint32_t bB, int kk,
                          uint32_t af[4][4], uint32_t bf[8][2]) {
        const uint32_t arow = aB + (warp_m * 64 + lr + 8 * s1) * HROWB
                                 + (kk + 8 * s2) * 2;
#pragma unroll
        for (int mt = 0; mt < 4; mt++)
            ldmx4(af[mt][0], af[mt][1], af[mt][2], af[mt][3],
                  arow + mt * 16 * HROWB);
        const uint32_t brow = bB + (warp_n * 64 + knt * 8 + lr) * HROWB
                                 + (kk + kkh * 8) * 2;
#pragma unroll
        for (int i = 0; i < 4; i++)
            ldmx4(bf[2 * i][0], bf[2 * i][1], bf[2 * i + 1][0], bf[2 * i + 1][1],
                  brow + i * 16 * HROWB);
    };

    const int NT = K / HTK;
    load_tile(0, 0);

    uint32_t af[2][4][4];
    uint32_t bf[2][8][2];

    for (int t = 0; t < NT; t++) {
        if (t + 1 < NT) {
            load_tile((t + 1) & 1, (t + 1) * HTK);
            CP_WAIT(1);
        } else {
            CP_WAIT(0);
        }
        __syncthreads();

        const uint32_t aB = sb + (t & 1) * HSTAGE;
        const uint32_t bB = aB + HATILE;

        load_frags(aB, bB, 0, af[0], bf[0]);
#pragma unroll
        for (int ks = 0; ks < 4; ks++) {
            const int cur = ks & 1;
            if (ks < 3)
                load_frags(aB, bB, (ks + 1) * 16, af[cur ^ 1], bf[cur ^ 1]);
#pragma unroll
            for (int mt = 0; mt < 4; mt++)
#pragma unroll
                for (int nt = 0; nt < 8; nt++)
                    mma_16n8k16_f16(c[mt][nt], af[cur][mt], bf[cur][nt]);
        }
        __syncthreads();
    }

#pragma unroll
    for (int mt = 0; mt < 4; mt++) {
        const int row = m0 + warp_m * 64 + mt * 16 + g;
#pragma unroll
        for (int nt = 0; nt < 8; nt++) {
            const int col = n0 + warp_n * 64 + nt * 8 + tig * 2;
            const float bx = bias[col];
            const float by = bias[col + 1];
            if (HALF_OUT) {
                __half* C = (__half*)Cout;
                *(__half2*)(C + (size_t)row * N + col) =
                    __floats2half2_rn(c[mt][nt][0] + bx, c[mt][nt][1] + by);
                *(__half2*)(C + (size_t)(row + 8) * N + col) =
                    __floats2half2_rn(c[mt][nt][2] + bx, c[mt][nt][3] + by);
            } else {
                float* C = (float*)Cout;
                *(float2*)(C + (size_t)row * N + col) =
                    make_float2(c[mt][nt][0] + bx, c[mt][nt][1] + by);
                *(float2*)(C + (size_t)(row + 8) * N + col) =
                    make_float2(c[mt][nt][2] + bx, c[mt][nt][3] + by);
            }
        }
    }
}

// ===========================================================================
// fp16 flash attention (unchanged from R10/R11, passing).
// ===========================================================================
#define FAS       144
#define FA_Q      0
#define FA_TILE   (64 * FAS)
#define FA_K      FA_TILE
#define FA_V      (FA_K + 2 * FA_TILE)
#define FA_SMEM   (FA_V + 2 * FA_TILE)      // 46080 B

__global__ __launch_bounds__(128) void flash_attn_f16(
    const __half* __restrict__ qkv, __half* __restrict__ out)
{
    extern __shared__ char smem[];
    const uint32_t sb = smem_u32(smem);
    const int tid  = threadIdx.x;
    const int wid  = tid >> 5;
    const int lane = tid & 31;
    const int g    = lane >> 2;
    const int tig  = lane & 3;
    const int q0   = blockIdx.x * 64;
    const int h    = blockIdx.y;
    const int b    = blockIdx.z;

    const __half* qb = qkv + (size_t)b * SEQ * QKVDIM + (size_t)h * HDIM;
    const __half* kb = qb + DIM;
    const __half* vb = qb + 2 * DIM;

#pragma unroll
    for (int i = 0; i < 4; i++) {
        const int idx = i * 128 + tid;
        const int row = idx >> 3;
        const int seg = idx & 7;
        cp16(sb + FA_Q + row * FAS + seg * 16,
             qb + (size_t)(q0 + row) * QKVDIM + seg * 8);
    }
    CP_COMMIT();

    auto load_kv = [&](int slot, int jt) {
        const int j0 = jt * 64;
        const uint32_t kB = sb + FA_K + slot * FA_TILE;
        const uint32_t vB = sb + FA_V + slot * FA_TILE;
#pragma unroll
        for (int i = 0; i < 4; i++) {
            const int idx = i * 128 + tid;
            const int row = idx >> 3;
            const int seg = idx & 7;
            cp16(kB + row * FAS + seg * 16, kb + (size_t)(j0 + row) * QKVDIM + seg * 8);
            cp16(vB + row * FAS + seg * 16, vb + (size_t)(j0 + row) * QKVDIM + seg * 8);
        }
        CP_COMMIT();
    };

    load_kv(0, 0);
    CP_WAIT(1);
    __syncthreads();

    const int lr  = lane & 7;
    const int grp = lane >> 3;

    uint32_t qf[4][4];
    {
        const uint32_t qbase = sb + FA_Q + (wid * 16) * FAS;
        const int s1 = grp & 1;
        const int s2 = grp >> 1;
        const __half2 sc = __float2half2_rn(0.03125f);
#pragma unroll
        for (int ks = 0; ks < 4; ks++) {
            const uint32_t addr = qbase + (lr + 8 * s1) * FAS + (ks * 16 + 8 * s2) * 2;
            ldmx4(qf[ks][0], qf[ks][1], qf[ks][2], qf[ks][3], addr);
#pragma unroll
            for (int j = 0; j < 4; j++) {
                __half2 v = *(__half2*)&qf[ks][j];
                v = __hmul2(v, sc);
                qf[ks][j] = *(uint32_t*)&v;
            }
        }
    }

    float o[8][4];
#pragma unroll
    for (int nt = 0; nt < 8; nt++)
#pragma unroll
        for (int r = 0; r < 4; r++) o[nt][r] = 0.0f;
    float m_r[2] = {-1e30f, -1e30f};
    float l_r[2] = {0.0f, 0.0f};

    const int knt = grp >> 1;
    const int kkh = grp & 1;

    for (int jt = 0; jt < SEQ / 64; jt++) {
        if (jt + 1 < SEQ / 64) {
            load_kv((jt + 1) & 1, jt + 1);
            CP_WAIT(1);
        } else {
            CP_WAIT(0);
        }
        __syncthreads();

        const uint32_t kB = sb + FA_K + (jt & 1) * FA_TILE;
        const uint32_t vB = sb + FA_V + (jt & 1) * FA_TILE;

        float c[8][4];
#pragma unroll
        for (int nt = 0; nt < 8; nt++)
#pragma unroll
            for (int r = 0; r < 4; r++) c[nt][r] = 0.0f;

#pragma unroll
        for (int ks = 0; ks < 4; ks++) {
            uint32_t kf[8][2];
#pragma unroll
            for (int i = 0; i < 4; i++) {
                const uint32_t addr =
                    kB + ((2 * i + knt) * 8 + lr) * FAS + (ks * 16 + kkh * 8) * 2;
                ldmx4(kf[2 * i][0], kf[2 * i][1], kf[2 * i + 1][0], kf[2 * i + 1][1], addr);
            }
#pragma unroll
            for (int nt = 0; nt < 8; nt++)
                mma_16n8k16_f16(c[nt], qf[ks], kf[nt]);
        }

#pragma unroll
        for (int r = 0; r < 2; r++) {
            float mx = -1e30f;
#pragma unroll
            for (int nt = 0; nt < 8; nt++) {
                mx = fmaxf(mx, c[nt][2 * r]);
                mx = fmaxf(mx, c[nt][2 * r + 1]);
            }
            mx = fmaxf(mx, __shfl_xor_sync(0xffffffffu, mx, 1));
            mx = fmaxf(mx, __shfl_xor_sync(0xffffffffu, mx, 2));
            const float mnew  = fmaxf(m_r[r], mx);
            const float alpha = __expf(m_r[r] - mnew);
            float sum = 0.0f;
#pragma unroll
            for (int nt = 0; nt < 8; nt++) {
                const float p0 = __expf(c[nt][2 * r]     - mnew);
                const float p1 = __expf(c[nt][2 * r + 1] - mnew);
                c[nt][2 * r] = p0; c[nt][2 * r + 1] = p1;
                sum += p0 + p1;
            }
            sum += __shfl_xor_sync(0xffffffffu, sum, 1);
            sum += __shfl_xor_sync(0xffffffffu, sum, 2);
            l_r[r] = l_r[r] * alpha + sum;
            m_r[r] = mnew;
#pragma unroll
            for (int nt = 0; nt < 8; nt++) {
                o[nt][2 * r]     *= alpha;
                o[nt][2 * r + 1] *= alpha;
            }
        }

#pragma unroll
        for (int ks = 0; ks < 4; ks++) {
            uint32_t pa[4];
            {
                __half2 p0 = __floats2half2_rn(c[2 * ks][0],     c[2 * ks][1]);
                __half2 p1 = __floats2half2_rn(c[2 * ks][2],     c[2 * ks][3]);
                __half2 p2 = __floats2half2_rn(c[2 * ks + 1][0], c[2 * ks + 1][1]);
                __half2 p3 = __floats2half2_rn(c[2 * ks + 1][2], c[2 * ks + 1][3]);
                pa[0] = *(uint32_t*)&p0;
                pa[1] = *(uint32_t*)&p1;
                pa[2] = *(uint32_t*)&p2;
                pa[3] = *(uint32_t*)&p3;
            }
            uint32_t vf[8][2];
#pragma unroll
            for (int i = 0; i < 4; i++) {
                const uint32_t addr =
                    vB + (ks * 16 + kkh * 8 + lr) * FAS + ((2 * i + knt) * 8) * 2;
                ldmx4t(vf[2 * i][0], vf[2 * i][1], vf[2 * i + 1][0], vf[2 * i + 1][1], addr);
            }
#pragma unroll
            for (int nt = 0; nt < 8; nt++)
                mma_16n8k16_f16(o[nt], pa, vf[nt]);
        }
        __syncthreads();
    }

    const float inv0 = 1.0f / l_r[0];
    const float inv1 = 1.0f / l_r[1];
    const size_t row0 = (size_t)b * SEQ + q0 + wid * 16 + g;
    const size_t row1 = row0 + 8;
#pragma unroll
    for (int nt = 0; nt < 8; nt++) {
        const int col = h * HDIM + nt * 8 + 2 * tig;
        *(__half2*)(out + row0 * DIM + col) =
            __floats2half2_rn(o[nt][0] * inv0, o[nt][1] * inv0);
        *(__half2*)(out + row1 * DIM + col) =
            __floats2half2_rn(o[nt][2] * inv1, o[nt][3] * inv1);
    }
}

// ===========================================================================
// Launch
// ===========================================================================
extern "C" void kernel_launch(void* const* d_in, const int* in_sizes, int n_in,
                              void* d_out, int out_size)
{
    const float* x    = (const float*)d_in[0];
    const float* Wqkv = (const float*)d_in[1];
    const float* bqkv = (const float*)d_in[2];
    const float* W1   = (const float*)d_in[3];
    const float* b1   = (const float*)d_in[4];
    float* out = (float*)d_out;

    __half *qkv_p, *attn_p, *xh_p, *wh_p, *w1h_p;
    cudaGetSymbolAddress((void**)&qkv_p,  g_qkv_h);
    cudaGetSymbolAddress((void**)&attn_p, g_attn_h);
    cudaGetSymbolAddress((void**)&xh_p,   g_xh);
    cudaGetSymbolAddress((void**)&wh_p,   g_wh);
    cudaGetSymbolAddress((void**)&w1h_p,  g_w1h);

    cudaFuncSetAttribute(gemm_mma_f16<true>,
                         cudaFuncAttributeMaxDynamicSharedMemorySize, HGEMM_SMEM);
    cudaFuncSetAttribute(gemm_mma_f16<false>,
                         cudaFuncAttributeMaxDynamicSharedMemorySize, HGEMM_SMEM);
    cudaFuncSetAttribute(flash_attn_f16,
                         cudaFuncAttributeMaxDynamicSharedMemorySize, FA_SMEM);

    // 0) one fused conversion pass: x, Wqkv, W1 -> fp16
    to_half_all<<<(NCONV4 + 255) / 256, 256>>>(x, Wqkv, W1, xh_p, wh_p, w1h_p);

    // 1) QKV projection -> fp16 qkv
    {
        dim3 grid(QKVDIM / 256, ROWS / 128);
        gemm_mma_f16<true><<<grid, 256, HGEMM_SMEM>>>(xh_p, wh_p, bqkv, qkv_p,
                                                      ROWS, QKVDIM, DIM);
    }

    // 2) fp16 flash attention -> fp16 attn
    {
        dim3 grid(SEQ / 64, HEADS, BATCH);
        flash_attn_f16<<<grid, 128, FA_SMEM>>>(qkv_p, attn_p);
    }

    // 3) Output projection -> fp32 out
    {
        dim3 grid(DIM / 256, ROWS / 128);
        gemm_mma_f16<false><<<grid, 256, HGEMM_SMEM>>>(attn_p, w1h_p, b1, out,
                                                       ROWS, DIM, DIM);
    }
}

// round 14
// speedup vs baseline: 1.1637x; 1.0003x over previous
#include <cuda_runtime.h>
#include <cuda_bf16.h>
#include <cuda_fp16.h>
#include <cstdint>

// ---------------------------------------------------------------------------
// Fused transformer block, fp32 in/out. All math on fp16 HMMA m16n8k16
// (fp32 accumulate). Pipeline runs at the measured sm_103a legacy-mma wall
// (~4 cyc per mma.sync per SM; tcgen05 unreachable via compute_103 target).
//   qkv = x @ Wqkv^T + bqkv   (4096x3072x1024)  -> fp16 qkv (Q pre-scaled /32)
//   attention: 16 heads, d=64                   -> fp16 flash attention
//   out = attn @ W1^T + b1    (4096x1024x1024)  -> fp32 out
// ---------------------------------------------------------------------------

#define BATCH   4
#define SEQ     1024
#define DIM     1024
#define HEADS   16
#define HDIM    64
#define ROWS    (BATCH * SEQ)      // 4096
#define QKVDIM  (3 * DIM)          // 3072

#define N_X   (ROWS * DIM)
#define N_W   (QKVDIM * DIM)
#define N_W1  (DIM * DIM)

__device__ __align__(256) __half g_qkv_h[ROWS * QKVDIM];
__device__ __align__(256) __half g_attn_h[ROWS * DIM];
__device__ __align__(256) __half g_xh[N_X];
__device__ __align__(256) __half g_wh[N_W];
__device__ __align__(256) __half g_w1h[N_W1];

// ===========================================================================
// helpers
// ===========================================================================
__device__ __forceinline__ uint32_t smem_u32(const void* p) {
    uint32_t a;
    asm("{ .reg .u64 t; cvta.to.shared.u64 t, %1; cvt.u32.u64 %0, t; }"
        : "=r"(a) : "l"(p));
    return a;
}
__device__ __forceinline__ void cp16(uint32_t dst, const void* src) {
    asm volatile("cp.async.cg.shared.global [%0], [%1], 16;" :: "r"(dst), "l"(src));
}
#define CP_COMMIT() asm volatile("cp.async.commit_group;" ::: "memory")
#define CP_WAIT(n)  asm volatile("cp.async.wait_group %0;" :: "n"(n) : "memory")

// fp16 m16n8k16, fp32 accumulate
__device__ __forceinline__ void mma_16n8k16_f16(
    float* c, const uint32_t* a, const uint32_t* b)
{
    asm volatile(
        "mma.sync.aligned.m16n8k16.row.col.f32.f16.f16.f32 "
        "{%0,%1,%2,%3}, {%4,%5,%6,%7}, {%8,%9}, {%0,%1,%2,%3};"
        : "+f"(c[0]), "+f"(c[1]), "+f"(c[2]), "+f"(c[3])
        : "r"(a[0]), "r"(a[1]), "r"(a[2]), "r"(a[3]), "r"(b[0]), "r"(b[1]));
}

__device__ __forceinline__ void ldmx4(
    uint32_t& r0, uint32_t& r1, uint32_t& r2, uint32_t& r3, uint32_t addr)
{
    asm volatile(
        "ldmatrix.sync.aligned.m8n8.x4.shared.b16 {%0,%1,%2,%3}, [%4];"
        : "=r"(r0), "=r"(r1), "=r"(r2), "=r"(r3) : "r"(addr));
}
__device__ __forceinline__ void ldmx4t(
    uint32_t& r0, uint32_t& r1, uint32_t& r2, uint32_t& r3, uint32_t addr)
{
    asm volatile(
        "ldmatrix.sync.aligned.m8n8.x4.trans.shared.b16 {%0,%1,%2,%3}, [%4];"
        : "=r"(r0), "=r"(r1), "=r"(r2), "=r"(r3) : "r"(addr));
}

// ===========================================================================
// fused fp32 -> fp16 conversion: one launch converts x, Wqkv, W1.
// ===========================================================================
#define NCONV4 ((N_X + N_W + N_W1) / 4)

__global__ __launch_bounds__(256) void to_half_all(
    const float* __restrict__ x, const float* __restrict__ w,
    const float* __restrict__ w1,
    __half* __restrict__ xh, __half* __restrict__ wh, __half* __restrict__ w1h)
{
    int i = blockIdx.x * blockDim.x + threadIdx.x;
    if (i >= NCONV4) return;
    const float* src;
    __half* dst;
    int j = i;
    if (j < N_X / 4)                   { src = x;  dst = xh;  }
    else if ((j -= N_X / 4) < N_W / 4) { src = w;  dst = wh;  }
    else { j -= N_W / 4;                 src = w1; dst = w1h; }
    float4 v = ((const float4*)src)[j];
    __half2* d = (__half2*)(dst + j * 4);
    d[0] = __floats2half2_rn(v.x, v.y);
    d[1] = __floats2half2_rn(v.z, v.w);
}

// ===========================================================================
// fp16 NT GEMM + bias: CTA tile 128x256, K-tile 64, 2-stage cp.async,
// 256 thr, warp grid 2x4, warp tile 64x64, ldmatrix.x4 fragments.
// MODE 0: fp32 out. MODE 1: fp16 out. MODE 2: fp16 out, QKV flavor —
//   columns < DIM (the Q block) are additionally scaled by 1/32 so the
//   attention kernel consumes Q directly.
// ===========================================================================
#define HTK       64
#define HROWB     144
#define HATILE    (128 * HROWB)
#define HBTILE    (256 * HROWB)
#define HSTAGE    (HATILE + HBTILE)          // 55296
#define HGEMM_SMEM (2 * HSTAGE)              // 110592 B

template <int MODE>
__global__ __launch_bounds__(256) void gemm_mma_f16(
    const __half* __restrict__ A, const __half* __restrict__ B,
    const float* __restrict__ bias, void* __restrict__ Cout,
    int M, int N, int K)
{
    extern __shared__ char smem[];
    const uint32_t sb = smem_u32(smem);
    const int tid    = threadIdx.x;
    const int wid    = tid >> 5;
    const int lane   = tid & 31;
    const int g      = lane >> 2;
    const int tig    = lane & 3;
    const int warp_m = wid & 1;
    const int warp_n = wid >> 1;
    const int m0     = blockIdx.y * 128;
    const int n0     = blockIdx.x * 256;

    const int lr  = lane & 7;
    const int grp = lane >> 3;
    const int s1  = grp & 1;
    const int s2  = grp >> 1;
    const int knt = grp >> 1;
    const int kkh = grp & 1;

    float c[4][8][4];
#pragma unroll
    for (int mt = 0; mt < 4; mt++)
#pragma unroll
        for (int nt = 0; nt < 8; nt++)
#pragma unroll
            for (int r = 0; r < 4; r++) c[mt][nt][r] = 0.0f;

    auto load_tile = [&](int slot, int k0) {
        const uint32_t aB = sb + slot * HSTAGE;
        const uint32_t bB = aB + HATILE;
#pragma unroll
        for (int i = 0; i < 4; i++) {
            const int idx = i * 256 + tid;
            const int row = idx >> 3;
            const int seg = idx & 7;
            cp16(aB + row * HROWB + seg * 16, A + (size_t)(m0 + row) * K + k0 + seg * 8);
        }
#pragma unroll
        for (int i = 0; i < 8; i++) {
            const int idx = i * 256 + tid;
            const int row = idx >> 3;
            const int seg = idx & 7;
            cp16(bB + row * HROWB + seg * 16, B + (size_t)(n0 + row) * K + k0 + seg * 8);
        }
        CP_COMMIT();
    };

    auto load_frags = [&](uint32_t aB, uint32_t bB, int kk,
                          uint32_t af[4][4], uint32_t bf[8][2]) {
        const uint32_t arow = aB + (warp_m * 64 + lr + 8 * s1) * HROWB
                                 + (kk + 8 * s2) * 2;
#pragma unroll
        for (int mt = 0; mt < 4; mt++)
            ldmx4(af[mt][0], af[mt][1], af[mt][2], af[mt][3],
                  arow + mt * 16 * HROWB);
        const uint32_t brow = bB + (warp_n * 64 + knt * 8 + lr) * HROWB
                                 + (kk + kkh * 8) * 2;
#pragma unroll
        for (int i = 0; i < 4; i++)
            ldmx4(bf[2 * i][0], bf[2 * i][1], bf[2 * i + 1][0], bf[2 * i + 1][1],
                  brow + i * 16 * HROWB);
    };

    const int NT = K / HTK;
    load_tile(0, 0);

    uint32_t af[2][4][4];
    uint32_t bf[2][8][2];

    for (int t = 0; t < NT; t++) {
        if (t + 1 < NT) {
            load_tile((t + 1) & 1, (t + 1) * HTK);
            CP_WAIT(1);
        } else {
            CP_WAIT(0);
        }
        __syncthreads();

        const uint32_t aB = sb + (t & 1) * HSTAGE;
        const uint32_t bB = aB + HATILE;

        load_frags(aB, bB, 0, af[0], bf[0]);
#pragma unroll
        for (int ks = 0; ks < 4; ks++) {
            const int cur = ks & 1;
            if (ks < 3)
                load_frags(aB, bB, (ks + 1) * 16, af[cur ^ 1], bf[cur ^ 1]);
#pragma unroll
            for (int mt = 0; mt < 4; mt++)
#pragma unroll
                for (int nt = 0; nt < 8; nt++)
                    mma_16n8k16_f16(c[mt][nt], af[cur][mt], bf[cur][nt]);
        }
        __syncthreads();
    }

#pragma unroll
    for (int mt = 0; mt < 4; mt++) {
        const int row = m0 + warp_m * 64 + mt * 16 + g;
#pragma unroll
        for (int nt = 0; nt < 8; nt++) {
            const int col = n0 + warp_n * 64 + nt * 8 + tig * 2;
            const float bx = bias[col];
            const float by = bias[col + 1];
            float v0 = c[mt][nt][0] + bx, v1 = c[mt][nt][1] + by;
            float v2 = c[mt][nt][2] + bx, v3 = c[mt][nt][3] + by;
            if (MODE == 2 && col < DIM) {       // Q block: fold 1/32 scale
                v0 *= 0.03125f; v1 *= 0.03125f;
                v2 *= 0.03125f; v3 *= 0.03125f;
            }
            if (MODE >= 1) {
                __half* C = (__half*)Cout;
                *(__half2*)(C + (size_t)row * N + col)       = __floats2half2_rn(v0, v1);
                *(__half2*)(C + (size_t)(row + 8) * N + col) = __floats2half2_rn(v2, v3);
            } else {
                float* C = (float*)Cout;
                *(float2*)(C + (size_t)row * N + col)       = make_float2(v0, v1);
                *(float2*)(C + (size_t)(row + 8) * N + col) = make_float2(v2, v3);
            }
        }
    }
}

// ===========================================================================
// fp16 flash attention (R10 structure; Q arrives pre-scaled by 1/32).
// ===========================================================================
#define FAS       144
#define FA_Q      0
#define FA_TILE   (64 * FAS)
#define FA_K      FA_TILE
#define FA_V      (FA_K + 2 * FA_TILE)
#define FA_SMEM   (FA_V + 2 * FA_TILE)      // 46080 B

__global__ __launch_bounds__(128) void flash_attn_f16(
    const __half* __restrict__ qkv, __half* __restrict__ out)
{
    extern __shared__ char smem[];
    const uint32_t sb = smem_u32(smem);
    const int tid  = threadIdx.x;
    const int wid  = tid >> 5;
    const int lane = tid & 31;
    const int g    = lane >> 2;
    const int tig  = lane & 3;
    const int q0   = blockIdx.x * 64;
    const int h    = blockIdx.y;
    const int b    = blockIdx.z;

    const __half* qb = qkv + (size_t)b * SEQ * QKVDIM + (size_t)h * HDIM;
    const __half* kb = qb + DIM;
    const __half* vb = qb + 2 * DIM;

#pragma unroll
    for (int i = 0; i < 4; i++) {
        const int idx = i * 128 + tid;
        const int row = idx >> 3;
        const int seg = idx & 7;
        cp16(sb + FA_Q + row * FAS + seg * 16,
             qb + (size_t)(q0 + row) * QKVDIM + seg * 8);
    }
    CP_COMMIT();

    auto load_kv = [&](int slot, int jt) {
        const int j0 = jt * 64;
        const uint32_t kB = sb + FA_K + slot * FA_TILE;
        const uint32_t vB = sb + FA_V + slot * FA_TILE;
#pragma unroll
        for (int i = 0; i < 4; i++) {
            const int idx = i * 128 + tid;
            const int row = idx >> 3;
            const int seg = idx & 7;
            cp16(kB + row * FAS + seg * 16, kb + (size_t)(j0 + row) * QKVDIM + seg * 8);
            cp16(vB + row * FAS + seg * 16, vb + (size_t)(j0 + row) * QKVDIM + seg * 8);
        }
        CP_COMMIT();
    };

    load_kv(0, 0);
    CP_WAIT(1);
    __syncthreads();

    const int lr  = lane & 7;
    const int grp = lane >> 3;

    // Q fragments (already scaled by 1/32 in the QKV epilogue)
    uint32_t qf[4][4];
    {
        const uint32_t qbase = sb + FA_Q + (wid * 16) * FAS;
        const int s1 = grp & 1;
        const int s2 = grp >> 1;
#pragma unroll
        for (int ks = 0; ks < 4; ks++) {
            const uint32_t addr = qbase + (lr + 8 * s1) * FAS + (ks * 16 + 8 * s2) * 2;
            ldmx4(qf[ks][0], qf[ks][1], qf[ks][2], qf[ks][3], addr);
        }
    }

    float o[8][4];
#pragma unroll
    for (int nt = 0; nt < 8; nt++)
#pragma unroll
        for (int r = 0; r < 4; r++) o[nt][r] = 0.0f;
    float m_r[2] = {-1e30f, -1e30f};
    float l_r[2] = {0.0f, 0.0f};

    const int knt = grp >> 1;
    const int kkh = grp & 1;

    for (int jt = 0; jt < SEQ / 64; jt++) {
        if (jt + 1 < SEQ / 64) {
            load_kv((jt + 1) & 1, jt + 1);
            CP_WAIT(1);
        } else {
            CP_WAIT(0);
        }
        __syncthreads();

        const uint32_t kB = sb + FA_K + (jt & 1) * FA_TILE;
        const uint32_t vB = sb + FA_V + (jt & 1) * FA_TILE;

        float c[8][4];
#pragma unroll
        for (int nt = 0; nt < 8; nt++)
#pragma unroll
            for (int r = 0; r < 4; r++) c[nt][r] = 0.0f;

#pragma unroll
        for (int ks = 0; ks < 4; ks++) {
            uint32_t kf[8][2];
#pragma unroll
            for (int i = 0; i < 4; i++) {
                const uint32_t addr =
                    kB + ((2 * i + knt) * 8 + lr) * FAS + (ks * 16 + kkh * 8) * 2;
                ldmx4(kf[2 * i][0], kf[2 * i][1], kf[2 * i + 1][0], kf[2 * i + 1][1], addr);
            }
#pragma unroll
            for (int nt = 0; nt < 8; nt++)
                mma_16n8k16_f16(c[nt], qf[ks], kf[nt]);
        }

#pragma unroll
        for (int r = 0; r < 2; r++) {
            float mx = -1e30f;
#pragma unroll
            for (int nt = 0; nt < 8; nt++) {
                mx = fmaxf(mx, c[nt][2 * r]);
                mx = fmaxf(mx, c[nt][2 * r + 1]);
            }
            mx = fmaxf(mx, __shfl_xor_sync(0xffffffffu, mx, 1));
            mx = fmaxf(mx, __shfl_xor_sync(0xffffffffu, mx, 2));
            const float mnew  = fmaxf(m_r[r], mx);
            const float alpha = __expf(m_r[r] - mnew);
            float sum = 0.0f;
#pragma unroll
            for (int nt = 0; nt < 8; nt++) {
                const float p0 = __expf(c[nt][2 * r]     - mnew);
                const float p1 = __expf(c[nt][2 * r + 1] - mnew);
                c[nt][2 * r] = p0; c[nt][2 * r + 1] = p1;
                sum += p0 + p1;
            }
            sum += __shfl_xor_sync(0xffffffffu, sum, 1);
            sum += __shfl_xor_sync(0xffffffffu, sum, 2);
            l_r[r] = l_r[r] * alpha + sum;
            m_r[r] = mnew;
#pragma unroll
            for (int nt = 0; nt < 8; nt++) {
                o[nt][2 * r]     *= alpha;
                o[nt][2 * r + 1] *= alpha;
            }
        }

#pragma unroll
        for (int ks = 0; ks < 4; ks++) {
            uint32_t pa[4];
            {
                __half2 p0 = __floats2half2_rn(c[2 * ks][0],     c[2 * ks][1]);
                __half2 p1 = __floats2half2_rn(c[2 * ks][2],     c[2 * ks][3]);
                __half2 p2 = __floats2half2_rn(c[2 * ks + 1][0], c[2 * ks + 1][1]);
                __half2 p3 = __floats2half2_rn(c[2 * ks + 1][2], c[2 * ks + 1][3]);
                pa[0] = *(uint32_t*)&p0;
                pa[1] = *(uint32_t*)&p1;
                pa[2] = *(uint32_t*)&p2;
                pa[3] = *(uint32_t*)&p3;
            }
            uint32_t vf[8][2];
#pragma unroll
            for (int i = 0; i < 4; i++) {
                const uint32_t addr =
                    vB + (ks * 16 + kkh * 8 + lr) * FAS + ((2 * i + knt) * 8) * 2;
                ldmx4t(vf[2 * i][0], vf[2 * i][1], vf[2 * i + 1][0], vf[2 * i + 1][1], addr);
            }
#pragma unroll
            for (int nt = 0; nt < 8; nt++)
                mma_16n8k16_f16(o[nt], pa, vf[nt]);
        }
        __syncthreads();
    }

    const float inv0 = 1.0f / l_r[0];
    const float inv1 = 1.0f / l_r[1];
    const size_t row0 = (size_t)b * SEQ + q0 + wid * 16 + g;
    const size_t row1 = row0 + 8;
#pragma unroll
    for (int nt = 0; nt < 8; nt++) {
        const int col = h * HDIM + nt * 8 + 2 * tig;
        *(__half2*)(out + row0 * DIM + col) =
            __floats2half2_rn(o[nt][0] * inv0, o[nt][1] * inv0);
        *(__half2*)(out + row1 * DIM + col) =
            __floats2half2_rn(o[nt][2] * inv1, o[nt][3] * inv1);
    }
}

// ===========================================================================
// Launch
// ===========================================================================
extern "C" void kernel_launch(void* const* d_in, const int* in_sizes, int n_in,
                              void* d_out, int out_size)
{
    const float* x    = (const float*)d_in[0];
    const float* Wqkv = (const float*)d_in[1];
    const float* bqkv = (const float*)d_in[2];
    const float* W1   = (const float*)d_in[3];
    const float* b1   = (const float*)d_in[4];
    float* out = (float*)d_out;

    __half *qkv_p, *attn_p, *xh_p, *wh_p, *w1h_p;
    cudaGetSymbolAddress((void**)&qkv_p,  g_qkv_h);
    cudaGetSymbolAddress((void**)&attn_p, g_attn_h);
    cudaGetSymbolAddress((void**)&xh_p,   g_xh);
    cudaGetSymbolAddress((void**)&wh_p,   g_wh);
    cudaGetSymbolAddress((void**)&w1h_p,  g_w1h);

    cudaFuncSetAttribute(gemm_mma_f16<0>,
                         cudaFuncAttributeMaxDynamicSharedMemorySize, HGEMM_SMEM);
    cudaFuncSetAttribute(gemm_mma_f16<2>,
                         cudaFuncAttributeMaxDynamicSharedMemorySize, HGEMM_SMEM);
    cudaFuncSetAttribute(flash_attn_f16,
                         cudaFuncAttributeMaxDynamicSharedMemorySize, FA_SMEM);

    // 0) one fused conversion pass: x, Wqkv, W1 -> fp16
    to_half_all<<<(NCONV4 + 255) / 256, 256>>>(x, Wqkv, W1, xh_p, wh_p, w1h_p);

    // 1) QKV projection -> fp16 qkv (Q block pre-scaled by 1/32)
    {
        dim3 grid(QKVDIM / 256, ROWS / 128);
        gemm_mma_f16<2><<<grid, 256, HGEMM_SMEM>>>(xh_p, wh_p, bqkv, qkv_p,
                                                   ROWS, QKVDIM, DIM);
    }

    // 2) fp16 flash attention -> fp16 attn
    {
        dim3 grid(SEQ / 64, HEADS, BATCH);
        flash_attn_f16<<<grid, 128, FA_SMEM>>>(qkv_p, attn_p);
    }

    // 3) Output projection -> fp32 out
    {
        dim3 grid(DIM / 256, ROWS / 128);
        gemm_mma_f16<0><<<grid, 256, HGEMM_SMEM>>>(attn_p, w1h_p, b1, out,
                                                   ROWS, DIM, DIM);
    }
}

// round 15
// speedup vs baseline: 1.1774x; 1.0117x over previous
#include <cuda_runtime.h>
#include <cuda_bf16.h>
#include <cuda_fp16.h>
#include <cstdint>

// ---------------------------------------------------------------------------
// Fused transformer block, fp32 in/out. All math on fp16 HMMA m16n8k16
// (fp32 accumulate), running at the sm_103a mma.sync wall (~512 MACs/cyc/SM).
// R15: tile shapes retuned for wave balance on 148 SMs:
//   QKV: 128x64 CTA tiles, 3 CTAs/SM  (T=1536, 6% quantization)
//   proj: 64x64 CTA tiles, 6 CTAs/SM  (T=1024, 1.2% quantization)
// ---------------------------------------------------------------------------

#define BATCH   4
#define SEQ     1024
#define DIM     1024
#define HEADS   16
#define HDIM    64
#define ROWS    (BATCH * SEQ)      // 4096
#define QKVDIM  (3 * DIM)          // 3072

#define N_X   (ROWS * DIM)
#define N_W   (QKVDIM * DIM)
#define N_W1  (DIM * DIM)

__device__ __align__(256) __half g_qkv_h[ROWS * QKVDIM];
__device__ __align__(256) __half g_attn_h[ROWS * DIM];
__device__ __align__(256) __half g_xh[N_X];
__device__ __align__(256) __half g_wh[N_W];
__device__ __align__(256) __half g_w1h[N_W1];

// ===========================================================================
// helpers
// ===========================================================================
__device__ __forceinline__ uint32_t smem_u32(const void* p) {
    uint32_t a;
    asm("{ .reg .u64 t; cvta.to.shared.u64 t, %1; cvt.u32.u64 %0, t; }"
        : "=r"(a) : "l"(p));
    return a;
}
__device__ __forceinline__ void cp16(uint32_t dst, const void* src) {
    asm volatile("cp.async.cg.shared.global [%0], [%1], 16;" :: "r"(dst), "l"(src));
}
#define CP_COMMIT() asm volatile("cp.async.commit_group;" ::: "memory")
#define CP_WAIT(n)  asm volatile("cp.async.wait_group %0;" :: "n"(n) : "memory")

// fp16 m16n8k16, fp32 accumulate
__device__ __forceinline__ void mma_16n8k16_f16(
    float* c, const uint32_t* a, const uint32_t* b)
{
    asm volatile(
        "mma.sync.aligned.m16n8k16.row.col.f32.f16.f16.f32 "
        "{%0,%1,%2,%3}, {%4,%5,%6,%7}, {%8,%9}, {%0,%1,%2,%3};"
        : "+f"(c[0]), "+f"(c[1]), "+f"(c[2]), "+f"(c[3])
        : "r"(a[0]), "r"(a[1]), "r"(a[2]), "r"(a[3]), "r"(b[0]), "r"(b[1]));
}

__device__ __forceinline__ void ldmx4(
    uint32_t& r0, uint32_t& r1, uint32_t& r2, uint32_t& r3, uint32_t addr)
{
    asm volatile(
        "ldmatrix.sync.aligned.m8n8.x4.shared.b16 {%0,%1,%2,%3}, [%4];"
        : "=r"(r0), "=r"(r1), "=r"(r2), "=r"(r3) : "r"(addr));
}
__device__ __forceinline__ void ldmx4t(
    uint32_t& r0, uint32_t& r1, uint32_t& r2, uint32_t& r3, uint32_t addr)
{
    asm volatile(
        "ldmatrix.sync.aligned.m8n8.x4.trans.shared.b16 {%0,%1,%2,%3}, [%4];"
        : "=r"(r0), "=r"(r1), "=r"(r2), "=r"(r3) : "r"(addr));
}

// ===========================================================================
// fused fp32 -> fp16 conversion: one launch converts x, Wqkv, W1.
// ===========================================================================
#define NCONV4 ((N_X + N_W + N_W1) / 4)

__global__ __launch_bounds__(256) void to_half_all(
    const float* __restrict__ x, const float* __restrict__ w,
    const float* __restrict__ w1,
    __half* __restrict__ xh, __half* __restrict__ wh, __half* __restrict__ w1h)
{
    int i = blockIdx.x * blockDim.x + threadIdx.x;
    if (i >= NCONV4) return;
    const float* src;
    __half* dst;
    int j = i;
    if (j < N_X / 4)                   { src = x;  dst = xh;  }
    else if ((j -= N_X / 4) < N_W / 4) { src = w;  dst = wh;  }
    else { j -= N_W / 4;                 src = w1; dst = w1h; }
    float4 v = ((const float4*)src)[j];
    __half2* d = (__half2*)(dst + j * 4);
    d[0] = __floats2half2_rn(v.x, v.y);
    d[1] = __floats2half2_rn(v.z, v.w);
}

// ===========================================================================
// Tile-templated fp16 NT GEMM + bias: C[M,N] = A[M,K] @ B[N,K]^T + bias[N].
// BM x BN CTA tile, WGM x WGN warp grid (warp tile 32x32: MT=2, NT=4),
// K-tile 64, 2-stage cp.async, ldmatrix.x4 fragments, 144 B smem row stride.
// MODE 0: fp32 out. MODE 2: fp16 out, cols < DIM scaled by 1/32 (Q block).
// ===========================================================================
#define HROWB 144

template <int BM, int BN, int WGM, int WGN, int NBLK, int MODE>
__global__ __launch_bounds__(WGM * WGN * 32, NBLK) void gemm_mma_f16(
    const __half* __restrict__ A, const __half* __restrict__ B,
    const float* __restrict__ bias, void* __restrict__ Cout,
    int M, int N, int K)
{
    constexpr int THREADS = WGM * WGN * 32;
    constexpr int WM = BM / WGM;          // 32
    constexpr int WN = BN / WGN;          // 32
    constexpr int MT = WM / 16;           // 2
    constexpr int NT = WN / 8;            // 4
    constexpr int ATILE = BM * HROWB;
    constexpr int STAGE = (BM + BN) * HROWB;
    constexpr int SA = BM * 8 / THREADS;  // A cp16 per thread
    constexpr int SB = BN * 8 / THREADS;  // B cp16 per thread

    extern __shared__ char smem[];
    const uint32_t sb = smem_u32(smem);
    const int tid    = threadIdx.x;
    const int wid    = tid >> 5;
    const int lane   = tid & 31;
    const int g      = lane >> 2;
    const int tig    = lane & 3;
    const int warp_m = wid % WGM;
    const int warp_n = wid / WGM;
    const int m0     = blockIdx.y * BM;
    const int n0     = blockIdx.x * BN;

    const int lr  = lane & 7;
    const int grp = lane >> 3;
    const int s1  = grp & 1;
    const int s2  = grp >> 1;
    const int knt = grp >> 1;
    const int kkh = grp & 1;

    float c[MT][NT][4];
#pragma unroll
    for (int mt = 0; mt < MT; mt++)
#pragma unroll
        for (int nt = 0; nt < NT; nt++)
#pragma unroll
            for (int r = 0; r < 4; r++) c[mt][nt][r] = 0.0f;

    auto load_tile = [&](int slot, int k0) {
        const uint32_t aB = sb + slot * STAGE;
        const uint32_t bB = aB + ATILE;
#pragma unroll
        for (int i = 0; i < SA; i++) {
            const int idx = i * THREADS + tid;
            const int row = idx >> 3;
            const int seg = idx & 7;
            cp16(aB + row * HROWB + seg * 16, A + (size_t)(m0 + row) * K + k0 + seg * 8);
        }
#pragma unroll
        for (int i = 0; i < SB; i++) {
            const int idx = i * THREADS + tid;
            const int row = idx >> 3;
            const int seg = idx & 7;
            cp16(bB + row * HROWB + seg * 16, B + (size_t)(n0 + row) * K + k0 + seg * 8);
        }
        CP_COMMIT();
    };

    const int NTI = K / 64;
    load_tile(0, 0);

    for (int t = 0; t < NTI; t++) {
        if (t + 1 < NTI) {
            load_tile((t + 1) & 1, (t + 1) * 64);
            CP_WAIT(1);
        } else {
            CP_WAIT(0);
        }
        __syncthreads();

        const uint32_t aB = sb + (t & 1) * STAGE;
        const uint32_t bB = aB + ATILE;

#pragma unroll
        for (int ks = 0; ks < 4; ks++) {
            uint32_t af[MT][4];
            uint32_t bf[NT][2];
            const uint32_t arow = aB + (warp_m * WM + lr + 8 * s1) * HROWB
                                     + (ks * 16 + 8 * s2) * 2;
#pragma unroll
            for (int mt = 0; mt < MT; mt++)
                ldmx4(af[mt][0], af[mt][1], af[mt][2], af[mt][3],
                      arow + mt * 16 * HROWB);
            const uint32_t brow = bB + (warp_n * WN + knt * 8 + lr) * HROWB
                                     + (ks * 16 + kkh * 8) * 2;
#pragma unroll
            for (int i = 0; i < NT / 2; i++)
                ldmx4(bf[2 * i][0], bf[2 * i][1], bf[2 * i + 1][0], bf[2 * i + 1][1],
                      brow + i * 16 * HROWB);
#pragma unroll
            for (int mt = 0; mt < MT; mt++)
#pragma unroll
                for (int nt = 0; nt < NT; nt++)
                    mma_16n8k16_f16(c[mt][nt], af[mt], bf[nt]);
        }
        __syncthreads();
    }

#pragma unroll
    for (int mt = 0; mt < MT; mt++) {
        const int row = m0 + warp_m * WM + mt * 16 + g;
#pragma unroll
        for (int nt = 0; nt < NT; nt++) {
            const int col = n0 + warp_n * WN + nt * 8 + tig * 2;
            const float bx = bias[col];
            const float by = bias[col + 1];
            float v0 = c[mt][nt][0] + bx, v1 = c[mt][nt][1] + by;
            float v2 = c[mt][nt][2] + bx, v3 = c[mt][nt][3] + by;
            if (MODE == 2 && col < DIM) {       // Q block: fold 1/32 scale
                v0 *= 0.03125f; v1 *= 0.03125f;
                v2 *= 0.03125f; v3 *= 0.03125f;
            }
            if (MODE == 2) {
                __half* C = (__half*)Cout;
                *(__half2*)(C + (size_t)row * N + col)       = __floats2half2_rn(v0, v1);
                *(__half2*)(C + (size_t)(row + 8) * N + col) = __floats2half2_rn(v2, v3);
            } else {
                float* C = (float*)Cout;
                *(float2*)(C + (size_t)row * N + col)       = make_float2(v0, v1);
                *(float2*)(C + (size_t)(row + 8) * N + col) = make_float2(v2, v3);
            }
        }
    }
}

// QKV: 128x64 tiles, 4x2 warps, 3 CTAs/SM
#define QKV_SMEM  (2 * (128 + 64) * HROWB)   // 55296
// proj: 64x64 tiles, 2x2 warps, 6 CTAs/SM
#define PRJ_SMEM  (2 * (64 + 64) * HROWB)    // 36864

// ===========================================================================
// fp16 flash attention (unchanged from R14; Q arrives pre-scaled by 1/32).
// ===========================================================================
#define FAS       144
#define FA_Q      0
#define FA_TILE   (64 * FAS)
#define FA_K      FA_TILE
#define FA_V      (FA_K + 2 * FA_TILE)
#define FA_SMEM   (FA_V + 2 * FA_TILE)      // 46080 B

__global__ __launch_bounds__(128) void flash_attn_f16(
    const __half* __restrict__ qkv, __half* __restrict__ out)
{
    extern __shared__ char smem[];
    const uint32_t sb = smem_u32(smem);
    const int tid  = threadIdx.x;
    const int wid  = tid >> 5;
    const int lane = tid & 31;
    const int g    = lane >> 2;
    const int tig  = lane & 3;
    const int q0   = blockIdx.x * 64;
    const int h    = blockIdx.y;
    const int b    = blockIdx.z;

    const __half* qb = qkv + (size_t)b * SEQ * QKVDIM + (size_t)h * HDIM;
    const __half* kb = qb + DIM;
    const __half* vb = qb + 2 * DIM;

#pragma unroll
    for (int i = 0; i < 4; i++) {
        const int idx = i * 128 + tid;
        const int row = idx >> 3;
        const int seg = idx & 7;
        cp16(sb + FA_Q + row * FAS + seg * 16,
             qb + (size_t)(q0 + row) * QKVDIM + seg * 8);
    }
    CP_COMMIT();

    auto load_kv = [&](int slot, int jt) {
        const int j0 = jt * 64;
        const uint32_t kB = sb + FA_K + slot * FA_TILE;
        const uint32_t vB = sb + FA_V + slot * FA_TILE;
#pragma unroll
        for (int i = 0; i < 4; i++) {
            const int idx = i * 128 + tid;
            const int row = idx >> 3;
            const int seg = idx & 7;
            cp16(kB + row * FAS + seg * 16, kb + (size_t)(j0 + row) * QKVDIM + seg * 8);
            cp16(vB + row * FAS + seg * 16, vb + (size_t)(j0 + row) * QKVDIM + seg * 8);
        }
        CP_COMMIT();
    };

    load_kv(0, 0);
    CP_WAIT(1);
    __syncthreads();

    const int lr  = lane & 7;
    const int grp = lane >> 3;

    uint32_t qf[4][4];
    {
        const uint32_t qbase = sb + FA_Q + (wid * 16) * FAS;
        const int s1 = grp & 1;
        const int s2 = grp >> 1;
#pragma unroll
        for (int ks = 0; ks < 4; ks++) {
            const uint32_t addr = qbase + (lr + 8 * s1) * FAS + (ks * 16 + 8 * s2) * 2;
            ldmx4(qf[ks][0], qf[ks][1], qf[ks][2], qf[ks][3], addr);
        }
    }

    float o[8][4];
#pragma unroll
    for (int nt = 0; nt < 8; nt++)
#pragma unroll
        for (int r = 0; r < 4; r++) o[nt][r] = 0.0f;
    float m_r[2] = {-1e30f, -1e30f};
    float l_r[2] = {0.0f, 0.0f};

    const int knt = grp >> 1;
    const int kkh = grp & 1;

    for (int jt = 0; jt < SEQ / 64; jt++) {
        if (jt + 1 < SEQ / 64) {
            load_kv((jt + 1) & 1, jt + 1);
            CP_WAIT(1);
        } else {
            CP_WAIT(0);
        }
        __syncthreads();

        const uint32_t kB = sb + FA_K + (jt & 1) * FA_TILE;
        const uint32_t vB = sb + FA_V + (jt & 1) * FA_TILE;

        float c[8][4];
#pragma unroll
        for (int nt = 0; nt < 8; nt++)
#pragma unroll
            for (int r = 0; r < 4; r++) c[nt][r] = 0.0f;

#pragma unroll
        for (int ks = 0; ks < 4; ks++) {
            uint32_t kf[8][2];
#pragma unroll
            for (int i = 0; i < 4; i++) {
                const uint32_t addr =
                    kB + ((2 * i + knt) * 8 + lr) * FAS + (ks * 16 + kkh * 8) * 2;
                ldmx4(kf[2 * i][0], kf[2 * i][1], kf[2 * i + 1][0], kf[2 * i + 1][1], addr);
            }
#pragma unroll
            for (int nt = 0; nt < 8; nt++)
                mma_16n8k16_f16(c[nt], qf[ks], kf[nt]);
        }

#pragma unroll
        for (int r = 0; r < 2; r++) {
            float mx = -1e30f;
#pragma unroll
            for (int nt = 0; nt < 8; nt++) {
                mx = fmaxf(mx, c[nt][2 * r]);
                mx = fmaxf(mx, c[nt][2 * r + 1]);
            }
            mx = fmaxf(mx, __shfl_xor_sync(0xffffffffu, mx, 1));
            mx = fmaxf(mx, __shfl_xor_sync(0xffffffffu, mx, 2));
            const float mnew  = fmaxf(m_r[r], mx);
            const float alpha = __expf(m_r[r] - mnew);
            float sum = 0.0f;
#pragma unroll
            for (int nt = 0; nt < 8; nt++) {
                const float p0 = __expf(c[nt][2 * r]     - mnew);
                const float p1 = __expf(c[nt][2 * r + 1] - mnew);
                c[nt][2 * r] = p0; c[nt][2 * r + 1] = p1;
                sum += p0 + p1;
            }
            sum += __shfl_xor_sync(0xffffffffu, sum, 1);
            sum += __shfl_xor_sync(0xffffffffu, sum, 2);
            l_r[r] = l_r[r] * alpha + sum;
            m_r[r] = mnew;
#pragma unroll
            for (int nt = 0; nt < 8; nt++) {
                o[nt][2 * r]     *= alpha;
                o[nt][2 * r + 1] *= alpha;
            }
        }

#pragma unroll
        for (int ks = 0; ks < 4; ks++) {
            uint32_t pa[4];
            {
                __half2 p0 = __floats2half2_rn(c[2 * ks][0],     c[2 * ks][1]);
                __half2 p1 = __floats2half2_rn(c[2 * ks][2],     c[2 * ks][3]);
                __half2 p2 = __floats2half2_rn(c[2 * ks + 1][0], c[2 * ks + 1][1]);
                __half2 p3 = __floats2half2_rn(c[2 * ks + 1][2], c[2 * ks + 1][3]);
                pa[0] = *(uint32_t*)&p0;
                pa[1] = *(uint32_t*)&p1;
                pa[2] = *(uint32_t*)&p2;
                pa[3] = *(uint32_t*)&p3;
            }
            uint32_t vf[8][2];
#pragma unroll
            for (int i = 0; i < 4; i++) {
                const uint32_t addr =
                    vB + (ks * 16 + kkh * 8 + lr) * FAS + ((2 * i + knt) * 8) * 2;
                ldmx4t(vf[2 * i][0], vf[2 * i][1], vf[2 * i + 1][0], vf[2 * i + 1][1], addr);
            }
#pragma unroll
            for (int nt = 0; nt < 8; nt++)
                mma_16n8k16_f16(o[nt], pa, vf[nt]);
        }
        __syncthreads();
    }

    const float inv0 = 1.0f / l_r[0];
    const float inv1 = 1.0f / l_r[1];
    const size_t row0 = (size_t)b * SEQ + q0 + wid * 16 + g;
    const size_t row1 = row0 + 8;
#pragma unroll
    for (int nt = 0; nt < 8; nt++) {
        const int col = h * HDIM + nt * 8 + 2 * tig;
        *(__half2*)(out + row0 * DIM + col) =
            __floats2half2_rn(o[nt][0] * inv0, o[nt][1] * inv0);
        *(__half2*)(out + row1 * DIM + col) =
            __floats2half2_rn(o[nt][2] * inv1, o[nt][3] * inv1);
    }
}

// ===========================================================================
// Launch
// ===========================================================================
extern "C" void kernel_launch(void* const* d_in, const int* in_sizes, int n_in,
                              void* d_out, int out_size)
{
    const float* x    = (const float*)d_in[0];
    const float* Wqkv = (const float*)d_in[1];
    const float* bqkv = (const float*)d_in[2];
    const float* W1   = (const float*)d_in[3];
    const float* b1   = (const float*)d_in[4];
    float* out = (float*)d_out;

    __half *qkv_p, *attn_p, *xh_p, *wh_p, *w1h_p;
    cudaGetSymbolAddress((void**)&qkv_p,  g_qkv_h);
    cudaGetSymbolAddress((void**)&attn_p, g_attn_h);
    cudaGetSymbolAddress((void**)&xh_p,   g_xh);
    cudaGetSymbolAddress((void**)&wh_p,   g_wh);
    cudaGetSymbolAddress((void**)&w1h_p,  g_w1h);

    cudaFuncSetAttribute((const void*)gemm_mma_f16<128, 64, 4, 2, 3, 2>,
                         cudaFuncAttributeMaxDynamicSharedMemorySize, QKV_SMEM);
    cudaFuncSetAttribute((const void*)gemm_mma_f16<64, 64, 2, 2, 6, 0>,
                         cudaFuncAttributeMaxDynamicSharedMemorySize, PRJ_SMEM);
    cudaFuncSetAttribute(flash_attn_f16,
                         cudaFuncAttributeMaxDynamicSharedMemorySize, FA_SMEM);

    // 0) one fused conversion pass: x, Wqkv, W1 -> fp16
    to_half_all<<<(NCONV4 + 255) / 256, 256>>>(x, Wqkv, W1, xh_p, wh_p, w1h_p);

    // 1) QKV projection -> fp16 qkv (Q block pre-scaled by 1/32)
    //    128x64 tiles: grid 48 x 32 = 1536 CTAs, 3 resident/SM
    {
        dim3 grid(QKVDIM / 64, ROWS / 128);
        gemm_mma_f16<128, 64, 4, 2, 3, 2><<<grid, 256, QKV_SMEM>>>(
            xh_p, wh_p, bqkv, qkv_p, ROWS, QKVDIM, DIM);
    }

    // 2) fp16 flash attention -> fp16 attn
    {
        dim3 grid(SEQ / 64, HEADS, BATCH);
        flash_attn_f16<<<grid, 128, FA_SMEM>>>(qkv_p, attn_p);
    }

    // 3) Output projection -> fp32 out
    //    64x64 tiles: grid 16 x 64 = 1024 CTAs, 6 resident/SM
    {
        dim3 grid(DIM / 64, ROWS / 64);
        gemm_mma_f16<64, 64, 2, 2, 6, 0><<<grid, 128, PRJ_SMEM>>>(
            attn_p, w1h_p, b1, out, ROWS, DIM, DIM);
    }
}